// round 8
// baseline (speedup 1.0000x reference)
#include <cuda_runtime.h>

typedef unsigned long long U64;

#define NUM_HEADS 8
#define HDIM 512
#define NGRAPH 256
#define TILE 16
#define XROW 520    // x tile row stride (floats); K-halves at offsets 0 and 260
#define HGAP 260
#define QROW 524    // qk row stride (floats); K-halves at 0 and 260

// ---------------- device scratch (no allocations allowed) ----------------
__device__ float g_qk[NUM_HEADS * HDIM];
__device__ int   g_start[NGRAPH + 1];
__device__ float g_y[NGRAPH][NUM_HEADS][HDIM];
__device__ float g_denom[NGRAPH][NUM_HEADS];
__device__ float g_att[NGRAPH][HDIM];

// ---------------- helpers ----------------
__device__ __forceinline__ U64 fma2(U64 a, U64 b, U64 c) {
    U64 d;
    asm("fma.rn.f32x2 %0, %1, %2, %3;" : "=l"(d) : "l"(a), "l"(b), "l"(c));
    return d;
}
__device__ __forceinline__ U64 dup2(float x) {
    U64 d; unsigned xi = __float_as_uint(x);
    asm("mov.b64 %0, {%1, %1};" : "=l"(d) : "r"(xi));
    return d;
}
__device__ __forceinline__ float lo2(U64 v) { return __uint_as_float((unsigned)(v & 0xffffffffu)); }
__device__ __forceinline__ float hi2(U64 v) { return __uint_as_float((unsigned)(v >> 32)); }

__device__ __forceinline__ void cpa16(void* dst, const void* src) {
    unsigned d = (unsigned)__cvta_generic_to_shared(dst);
    asm volatile("cp.async.cg.shared.global [%0], [%1], 16;\n" :: "r"(d), "l"(src));
}
#define CP_COMMIT() asm volatile("cp.async.commit_group;\n" ::: "memory")
#define CP_WAIT0()  asm volatile("cp.async.wait_group 0;\n" ::: "memory")

// ---------------- kernel 0: qk fold (64 CTAs, smem-staged coalesced) ----------------
__global__ __launch_bounds__(256) void qk_kernel(const float* __restrict__ q,
                                                 const float* __restrict__ kw) {
    __shared__ float tile[64 * 65];   // [d][c], stride 65 -> conflict-free scalar column reads
    __shared__ float qs[64];
    __shared__ float part[4][64];
    const int h = blockIdx.x >> 3, jb = blockIdx.x & 7;
    const int t = threadIdx.x;
    if (t < 64) qs[t] = q[h * 64 + t];
    for (int k = t; k < 1024; k += 256) {          // 64 rows x 16 chunks of 4 floats
        int r = k >> 4, cc = k & 15;
        float4 v = *(const float4*)&kw[(size_t)(h * 64 + r) * HDIM + jb * 64 + cc * 4];
        float* dst = &tile[r * 65 + cc * 4];
        dst[0] = v.x; dst[1] = v.y; dst[2] = v.z; dst[3] = v.w;
    }
    __syncthreads();
    const int c = t & 63, ds = t >> 6;
    float s = 0.f;
#pragma unroll
    for (int d = 0; d < 16; d++) s += qs[ds * 16 + d] * tile[(ds * 16 + d) * 65 + c];
    part[ds][c] = s;
    __syncthreads();
    if (t < 64)
        g_qk[h * HDIM + jb * 64 + t] =
            (part[0][t] + part[1][t] + part[2][t] + part[3][t]) * 0.125f;
}

// ---------------- kernel 1: segment boundaries from sorted batch ----------------
__global__ void bounds_kernel(const int* __restrict__ batch, int N) {
    int n = blockIdx.x * 256 + threadIdx.x;
    if (n >= N) return;
    int b = batch[n];
    int p = (n == 0) ? -1 : batch[n - 1];
    for (int g = p + 1; g <= b; g++) g_start[g] = n;
    if (n == N - 1)
        for (int g = b + 1; g <= NGRAPH; g++) g_start[g] = N;
}

// ---------------- kernel 2: main fused pass — cp.async double-buffered ----------------
// Phase A: s[n,h] = x[n]·qk[h] split across 2 K-halves (shfl-pair reduce); w = exp(s).
// Phase B: Y[h,:] += w[n,h]*x[n,:]; denom[h] += w.
// Thread map (phase A): kh = t&1 (K-half), hh = (t>>1)&7 (head), ng = t>>4 (tile row).
__global__ __launch_bounds__(256, 2)
void main_kernel(const float* __restrict__ x) {
    extern __shared__ float sm[];
    float* xs   = sm;                       // [2][TILE][XROW] = 16640
    float* qs   = sm + 2 * TILE * XROW;     // [8][QROW]       = 4192
    float* ws   = qs + 8 * QROW;            // [TILE][8]       = 128
    float* dred = ws + TILE * 8;            // [256]

    const int t = threadIdx.x;
    const int g = blockIdx.x;

    // stage qk with K-half gap layout (half 1 at +HGAP)
    for (int k = t; k < 8 * HDIM; k += 256) {
        int h = k >> 9, j = k & 511;
        qs[h * QROW + j + (j >= 256 ? 4 : 0)] = g_qk[k];
    }

    const int s0 = g_start[g];
    const int nn = g_start[g + 1] - s0;
    const int ntiles = (nn + TILE - 1) / TILE;

    const int kh = t & 1, hh = (t >> 1) & 7, ng = t >> 4;
    const int c0 = 2 * t;
    const int xoffb = c0 + (c0 >= 256 ? 4 : 0);

    U64 acc[2][4];
#pragma unroll
    for (int a = 0; a < 2; a++)
#pragma unroll
        for (int p = 0; p < 4; p++) acc[a][p] = 0ull;
    float dpart = 0.f;

    // tile loader: 16 rows x 128 chunks of 16B -> 8 cp.async per thread
#define LOAD_TILE(TB, BUF) do {                                              \
        float* dstb = xs + (BUF) * TILE * XROW;                              \
        int tcl = nn - (TB); if (tcl > TILE) tcl = TILE;                     \
        _Pragma("unroll")                                                    \
        for (int k = 0; k < 8; k++) {                                        \
            int idx = t + k * 256;                                           \
            int r = idx >> 7, cc = idx & 127;                                \
            int col4 = cc * 4;                                               \
            if (r < tcl)                                                     \
                cpa16(dstb + r * XROW + col4 + (col4 >= 256 ? 4 : 0),        \
                      &x[(size_t)(s0 + (TB) + r) * HDIM + col4]);            \
        }                                                                    \
    } while (0)

    if (ntiles > 0) LOAD_TILE(0, 0);
    CP_COMMIT();
    __syncthreads();   // covers qs staging

    for (int ti = 0; ti < ntiles; ti++) {
        CP_WAIT0();
        __syncthreads();                       // tile ti visible to all
        if (ti + 1 < ntiles) LOAD_TILE((ti + 1) * TILE, (ti + 1) & 1);
        CP_COMMIT();                           // (empty group ok on last tile)

        const int tc = min(TILE, nn - ti * TILE);

        // ---- Phase A: 256-dim half-dot per thread, pair-reduce via shfl ----
        {
            const float* xr = xs + (ti & 1) * TILE * XROW + ng * XROW + kh * HGAP;
            const float* qr = qs + hh * QROW + kh * HGAP;
            U64 a0 = 0, a1 = 0, a2 = 0, a3 = 0;
#pragma unroll 4
            for (int j = 0; j < 256; j += 8) {
                ulonglong2 xv0 = *(const ulonglong2*)&xr[j];
                ulonglong2 qv0 = *(const ulonglong2*)&qr[j];
                ulonglong2 xv1 = *(const ulonglong2*)&xr[j + 4];
                ulonglong2 qv1 = *(const ulonglong2*)&qr[j + 4];
                a0 = fma2(xv0.x, qv0.x, a0);
                a1 = fma2(xv0.y, qv0.y, a1);
                a2 = fma2(xv1.x, qv1.x, a2);
                a3 = fma2(xv1.y, qv1.y, a3);
            }
            float sh = lo2(a0) + hi2(a0) + lo2(a1) + hi2(a1)
                     + lo2(a2) + hi2(a2) + lo2(a3) + hi2(a3);
            sh += __shfl_xor_sync(~0u, sh, 1);      // combine K-halves
            if (kh == 0) {
                float w = (ng < tc) ? __expf(sh) : 0.f;
                ws[ng * 8 + hh] = w;
                dpart += w;
            }
        }
        __syncthreads();

        // ---- Phase B: rank-1 accumulate into Y (2 cols x 8 heads per thread) ----
        {
            const float* xb = xs + (ti & 1) * TILE * XROW;
            for (int i = 0; i < tc; i++) {
                float2 xv = *(const float2*)&xb[i * XROW + xoffb];
                ulonglong2 w01 = *(const ulonglong2*)&ws[i * 8];
                ulonglong2 w23 = *(const ulonglong2*)&ws[i * 8 + 4];
                U64 xa = dup2(xv.x), xbv = dup2(xv.y);
                acc[0][0] = fma2(w01.x, xa, acc[0][0]);
                acc[0][1] = fma2(w01.y, xa, acc[0][1]);
                acc[0][2] = fma2(w23.x, xa, acc[0][2]);
                acc[0][3] = fma2(w23.y, xa, acc[0][3]);
                acc[1][0] = fma2(w01.x, xbv, acc[1][0]);
                acc[1][1] = fma2(w01.y, xbv, acc[1][1]);
                acc[1][2] = fma2(w23.x, xbv, acc[1][2]);
                acc[1][3] = fma2(w23.y, xbv, acc[1][3]);
            }
        }
        __syncthreads();
    }
#undef LOAD_TILE

    // write Y (coalesced float2 per head)
#pragma unroll
    for (int p = 0; p < 4; p++) {
        *(float2*)&g_y[g][2 * p][c0]     = make_float2(lo2(acc[0][p]), lo2(acc[1][p]));
        *(float2*)&g_y[g][2 * p + 1][c0] = make_float2(hi2(acc[0][p]), hi2(acc[1][p]));
    }

    // denom reduction — FIXED for the kh/hh/ng mapping:
    // head h's partials live in threads t = ng*16 + 2*h (kh = 0), ng = 0..15.
    dred[t] = dpart;
    __syncthreads();
    if (t < 8) {
        float s = 0.f;
#pragma unroll
        for (int k = 0; k < 16; k++) s += dred[k * 16 + 2 * t];
        g_denom[g][t] = s;
    }
}

// ---------------- kernel 3: v-projection (f32x2 + cp.async double-buffered weights) ----------------
// grid (32 graph-blocks of 8, 8 heads)
__global__ __launch_bounds__(256) void vproj_kernel(const float* __restrict__ vw,
                                                    const float* __restrict__ vb) {
    __shared__ float Yn[8][HDIM];          // normalized Y, 16KB
    __shared__ float wt[2][64][68];        // double-buffered weight chunk
    __shared__ float invs[8], nzf[8];
    const int gb = blockIdx.x, h = blockIdx.y, t = threadIdx.x;

    if (t < 8) {
        float d = g_denom[gb * 8 + t][h];
        invs[t] = d > 0.f ? 1.f / d : 0.f;
        nzf[t]  = d > 0.f ? 1.f : 0.f;
    }
    __syncthreads();

    for (int k = t * 4; k < 8 * HDIM; k += 1024) {
        int r = k >> 9, cidx = k & 511;
        float4 v = *(const float4*)&g_y[gb * 8 + r][h][cidx];
        float s = invs[r];
        v.x *= s; v.y *= s; v.z *= s; v.w *= s;
        *(float4*)&Yn[r][cidx] = v;
    }

#define LOAD_W(KC, BUF) do {                                                  \
        _Pragma("unroll")                                                     \
        for (int k = 0; k < 4; k++) {                                         \
            int idx = t + k * 256;                                            \
            int r = idx >> 4, cc = idx & 15;                                  \
            cpa16(&wt[BUF][r][cc * 4],                                        \
                  &vw[(size_t)(h * 64 + r) * HDIM + (KC) + cc * 4]);          \
        }                                                                     \
    } while (0)

    LOAD_W(0, 0);
    CP_COMMIT();

    const int c = t & 63, gq = t >> 6;     // outputs: (col c) x graphs {gq, gq+4}
    U64 acc[2][2] = {{0ull, 0ull}, {0ull, 0ull}};

    for (int ch = 0; ch < 8; ch++) {
        CP_WAIT0();
        __syncthreads();
        if (ch + 1 < 8) LOAD_W((ch + 1) * 64, (ch + 1) & 1);
        CP_COMMIT();

        const float* wr = &wt[ch & 1][c][0];
#pragma unroll
        for (int j = 0; j < 64; j += 4) {
            ulonglong2 w2 = *(const ulonglong2*)&wr[j];
            ulonglong2 ya = *(const ulonglong2*)&Yn[gq][ch * 64 + j];
            ulonglong2 yb = *(const ulonglong2*)&Yn[gq + 4][ch * 64 + j];
            acc[0][0] = fma2(w2.x, ya.x, acc[0][0]);
            acc[0][1] = fma2(w2.y, ya.y, acc[0][1]);
            acc[1][0] = fma2(w2.x, yb.x, acc[1][0]);
            acc[1][1] = fma2(w2.y, yb.y, acc[1][1]);
        }
        __syncthreads();
    }
#undef LOAD_W

    float b = vb[h * 64 + c];
    float ra = lo2(acc[0][0]) + hi2(acc[0][0]) + lo2(acc[0][1]) + hi2(acc[0][1]);
    float rb = lo2(acc[1][0]) + hi2(acc[1][0]) + lo2(acc[1][1]) + hi2(acc[1][1]);
    g_att[gb * 8 + gq][h * 64 + c]     = ra + nzf[gq] * b;
    g_att[gb * 8 + gq + 4][h * 64 + c] = rb + nzf[gq + 4] * b;
}

// ---------------- kernel 4: output projection (same structure) ----------------
// grid (32 graph-blocks of 8, 8 col-blocks of 64)
__global__ __launch_bounds__(256) void oproj_kernel(const float* __restrict__ ow,
                                                    const float* __restrict__ ob,
                                                    float* __restrict__ out) {
    __shared__ float As[8][HDIM];
    __shared__ float wt[2][64][68];
    const int gb = blockIdx.x, ib = blockIdx.y, t = threadIdx.x;

    for (int k = t * 4; k < 8 * HDIM; k += 1024) {
        int r = k >> 9, cidx = k & 511;
        *(float4*)&As[r][cidx] = *(const float4*)&g_att[gb * 8 + r][cidx];
    }

#define LOAD_W(KC, BUF) do {                                                  \
        _Pragma("unroll")                                                     \
        for (int k = 0; k < 4; k++) {                                         \
            int idx = t + k * 256;                                            \
            int r = idx >> 4, cc = idx & 15;                                  \
            cpa16(&wt[BUF][r][cc * 4],                                        \
                  &ow[(size_t)(ib * 64 + r) * HDIM + (KC) + cc * 4]);         \
        }                                                                     \
    } while (0)

    LOAD_W(0, 0);
    CP_COMMIT();

    const int c = t & 63, gq = t >> 6;
    U64 acc[2][2] = {{0ull, 0ull}, {0ull, 0ull}};

    for (int ch = 0; ch < 8; ch++) {
        CP_WAIT0();
        __syncthreads();
        if (ch + 1 < 8) LOAD_W((ch + 1) * 64, (ch + 1) & 1);
        CP_COMMIT();

        const float* wr = &wt[ch & 1][c][0];
#pragma unroll
        for (int j = 0; j < 64; j += 4) {
            ulonglong2 w2 = *(const ulonglong2*)&wr[j];
            ulonglong2 ya = *(const ulonglong2*)&As[gq][ch * 64 + j];
            ulonglong2 yb = *(const ulonglong2*)&As[gq + 4][ch * 64 + j];
            acc[0][0] = fma2(w2.x, ya.x, acc[0][0]);
            acc[0][1] = fma2(w2.y, ya.y, acc[0][1]);
            acc[1][0] = fma2(w2.x, yb.x, acc[1][0]);
            acc[1][1] = fma2(w2.y, yb.y, acc[1][1]);
        }
        __syncthreads();
    }
#undef LOAD_W

    float b = ob[ib * 64 + c];
    float ra = lo2(acc[0][0]) + hi2(acc[0][0]) + lo2(acc[0][1]) + hi2(acc[0][1]);
    float rb = lo2(acc[1][0]) + hi2(acc[1][0]) + lo2(acc[1][1]) + hi2(acc[1][1]);
    out[(size_t)(gb * 8 + gq) * HDIM + ib * 64 + c]       = ra + b;
    out[(size_t)(gb * 8 + gq + 4) * HDIM + ib * 64 + c]   = rb + b;
}

// ---------------- kernel 5: layer norm (in place on d_out) ----------------
__global__ void ln_kernel(const float* __restrict__ gam, const float* __restrict__ bet,
                          float* __restrict__ out) {
    __shared__ float red1[8], red2[8], stats[2];
    int r = blockIdx.x, t = threadIdx.x;
    float v0 = out[(size_t)r * HDIM + t];
    float v1 = out[(size_t)r * HDIM + t + 256];
    float s1 = v0 + v1, s2 = v0 * v0 + v1 * v1;
#pragma unroll
    for (int o = 16; o; o >>= 1) {
        s1 += __shfl_xor_sync(~0u, s1, o);
        s2 += __shfl_xor_sync(~0u, s2, o);
    }
    if ((t & 31) == 0) { red1[t >> 5] = s1; red2[t >> 5] = s2; }
    __syncthreads();
    if (t == 0) {
        float a = 0.f, b = 0.f;
        for (int k = 0; k < 8; k++) { a += red1[k]; b += red2[k]; }
        float mu = a * (1.f / 512.f);
        stats[0] = mu;
        stats[1] = rsqrtf(b * (1.f / 512.f) - mu * mu + 1e-5f);
    }
    __syncthreads();
    float mu = stats[0], rs = stats[1];
    out[(size_t)r * HDIM + t]       = (v0 - mu) * rs * gam[t] + bet[t];
    out[(size_t)r * HDIM + t + 256] = (v1 - mu) * rs * gam[t + 256] + bet[t + 256];
}

// ---------------- launch ----------------
extern "C" void kernel_launch(void* const* d_in, const int* in_sizes, int n_in,
                              void* d_out, int out_size) {
    const float* x     = (const float*)d_in[0];
    const int*   batch = (const int*)d_in[1];
    const float* q     = (const float*)d_in[2];
    const float* kw    = (const float*)d_in[3];
    // d_in[4] = k_b: cancels in segment softmax (per-head constant shift) — unused
    const float* vw    = (const float*)d_in[5];
    const float* vb    = (const float*)d_in[6];
    const float* ow    = (const float*)d_in[7];
    const float* ob    = (const float*)d_in[8];
    const float* lng   = (const float*)d_in[9];
    const float* lnb   = (const float*)d_in[10];
    float* out = (float*)d_out;

    int N = in_sizes[0] / HDIM;

    qk_kernel<<<64, 256>>>(q, kw);
    bounds_kernel<<<(N + 255) / 256, 256>>>(batch, N);

    size_t smem = (2 * TILE * XROW + 8 * QROW + TILE * 8 + 256) * sizeof(float);
    cudaFuncSetAttribute(main_kernel, cudaFuncAttributeMaxDynamicSharedMemorySize, (int)smem);
    main_kernel<<<NGRAPH, 256, smem>>>(x);

    vproj_kernel<<<dim3(32, NUM_HEADS), 256>>>(vw, vb);
    oproj_kernel<<<dim3(32, NUM_HEADS), 256>>>(ow, ob, out);
    ln_kernel<<<NGRAPH, 256>>>(lng, lnb, out);
}